// round 12
// baseline (speedup 1.0000x reference)
#include <cuda_runtime.h>
#include <cuda_fp16.h>
#include <cstdint>

#define MMV 2048
#define NNV 4096
#define KKV 4096

// Scratch (__device__ globals; no allocations allowed)
__device__ __align__(16) __half g_xh[(size_t)MMV * KKV];  // fp16(x)
__device__ __align__(16) __half g_wd[(size_t)KKV * NNV];  // fp16(s*(q-z)), [K][N]

// ---------------------------------------------------------------------------
// asm helpers
// ---------------------------------------------------------------------------
__device__ __forceinline__ void ldsm4(uint32_t* r, uint32_t addr) {
    asm volatile("ldmatrix.sync.aligned.m8n8.x4.shared.b16 {%0,%1,%2,%3}, [%4];"
                 : "=r"(r[0]), "=r"(r[1]), "=r"(r[2]), "=r"(r[3]) : "r"(addr));
}
__device__ __forceinline__ void ldsm4t(uint32_t* r, uint32_t addr) {
    asm volatile("ldmatrix.sync.aligned.m8n8.x4.trans.shared.b16 {%0,%1,%2,%3}, [%4];"
                 : "=r"(r[0]), "=r"(r[1]), "=r"(r[2]), "=r"(r[3]) : "r"(addr));
}
__device__ __forceinline__ void mma_f16(float* c, const uint32_t* a, const uint32_t* b) {
    asm volatile("mma.sync.aligned.m16n8k16.row.col.f32.f16.f16.f32 "
                 "{%0,%1,%2,%3}, {%4,%5,%6,%7}, {%8,%9}, {%0,%1,%2,%3};"
                 : "+f"(c[0]), "+f"(c[1]), "+f"(c[2]), "+f"(c[3])
                 : "r"(a[0]), "r"(a[1]), "r"(a[2]), "r"(a[3]), "r"(b[0]), "r"(b[1]));
}
__device__ __forceinline__ void cpa16(uint32_t s, const void* g) {
    asm volatile("cp.async.cg.shared.global [%0], [%1], 16;" :: "r"(s), "l"(g));
}
#define CP_COMMIT() asm volatile("cp.async.commit_group;" ::: "memory")
#define CP_WAIT1()  asm volatile("cp.async.wait_group 1;" ::: "memory")

// ---------------------------------------------------------------------------
// Fused prep: x->fp16; W unpack to fp16(s*(q-z))
// ---------------------------------------------------------------------------
__global__ void prep_kernel(const float4* __restrict__ x4,
                            const int* __restrict__ qw,
                            const float* __restrict__ zp,
                            const float* __restrict__ scales)
{
    if (blockIdx.x < 8192) {
        size_t i = (size_t)blockIdx.x * blockDim.x + threadIdx.x;   // over M*K/4
        float4 v = x4[i];
        __align__(8) __half h[4];
        h[0] = __float2half_rn(v.x); h[1] = __float2half_rn(v.y);
        h[2] = __float2half_rn(v.z); h[3] = __float2half_rn(v.w);
        ((uint2*)g_xh)[i] = *(uint2*)h;
    } else {
        int T = (blockIdx.x - 8192) * blockDim.x + threadIdx.x;     // < 512*2048
        int np = T & (NNV / 2 - 1);
        int kp = T >> 11;
        int g  = kp >> 4;
        int n0 = np * 2;
        float z0 = fminf(fmaxf(rintf(zp[g * NNV + n0]),     0.0f), 15.0f);
        float z1 = fminf(fmaxf(rintf(zp[g * NNV + n0 + 1]), 0.0f), 15.0f);
        float s0 = fminf(fmaxf(scales[g * NNV + n0],     1e-5f), 1e4f);
        float s1 = fminf(fmaxf(scales[g * NNV + n0 + 1], 1e-5f), 1e4f);
        int q0 = qw[(size_t)kp * NNV + n0];
        int q1 = qw[(size_t)kp * NNV + n0 + 1];
#pragma unroll
        for (int j = 0; j < 8; ++j) {
            float w0 = (float)((q0 >> (4 * j)) & 15);
            float w1 = (float)((q1 >> (4 * j)) & 15);
            __half2 o = __floats2half2_rn((w0 - z0) * s0, (w1 - z1) * s1);
            *(__half2*)(g_wd + (size_t)(kp * 8 + j) * NNV + n0) = o;
        }
    }
}

// ---------------------------------------------------------------------------
// Split-K=2 GEMM: C = xh @ Wd + bias (C pre-zeroed; both k-halves atomicAdd).
// CTA tile 64x128 x Khalf=2048, BK=64 -> 32 static iterations.
// 4 warps (2m x 2n), warp tile 32x64 — EXACT R9 microkernel/pipeline.
// Grid 32(n) x 32(m) x 2(khalf) = 2048 CTAs over 444 slots: 92.3% wave util.
// NS=3 stages x (A 8K | B 16K) = 73.7 KB smem; 3 CTAs/SM.
// ---------------------------------------------------------------------------
#define NS 3
#define STG_BYTES 24576
#define SMEM_TOTAL (NS * STG_BYTES)   // 73728

__global__ void __launch_bounds__(128, 3)
gemm_kernel(const float* __restrict__ bias,
            float* __restrict__ C)
{
    extern __shared__ __align__(16) char smem[];
    const uint32_t sb = (uint32_t)__cvta_generic_to_shared(smem);
    const int tid = threadIdx.x, lane = tid & 31, wid = tid >> 5;
    const int wm = wid & 1, wn = wid >> 1;
    const int m0 = blockIdx.y * 64, n0 = blockIdx.x * 128;
    const int kbase = blockIdx.z * 32;     // k-tile offset for this half

    // loader: A 64x64 fp16 (512 x 16B chunks), B 64x128 fp16 (1024 chunks)
    auto load_stage = [&](int kt, int st) {
        uint32_t base = sb + st * STG_BYTES;
#pragma unroll
        for (int j = 0; j < 4; ++j) {
            int q = tid + j * 128;
            int r = q >> 3, c = q & 7;
            uint32_t so = base + (uint32_t)(r * 8 + (c ^ (r & 7))) * 16;
            cpa16(so, g_xh + (size_t)(m0 + r) * KKV + kt * 64 + c * 8);
        }
#pragma unroll
        for (int j = 0; j < 8; ++j) {
            int q = tid + j * 128;
            int r = q >> 4, c = q & 15;
            uint32_t so = base + 8192 + (uint32_t)(r * 16 + (c ^ (r & 7))) * 16;
            cpa16(so, g_wd + (size_t)(kt * 64 + r) * NNV + n0 + c * 8);
        }
    };

    // prefill 2 stages
    load_stage(kbase + 0, 0); CP_COMMIT();
    load_stage(kbase + 1, 1); CP_COMMIT();

    // ldmatrix address precompute
    const int lane_r = lane & 15, chh = lane >> 4;
    uint32_t arow[2], axr[2];
#pragma unroll
    for (int t = 0; t < 2; ++t) {
        int r = wm * 32 + t * 16 + lane_r;
        arow[t] = (uint32_t)r * 128;            // 128 B per A row
        axr[t]  = (uint32_t)(r & 7);
    }
    const uint32_t xb = (uint32_t)(lane_r & 7);
    uint32_t bcol[4];
#pragma unroll
    for (int bb = 0; bb < 4; ++bb)
        bcol[bb] = (uint32_t)(wn * 8 + (((uint32_t)(bb * 2 + chh)) ^ xb)) * 16;
    uint32_t boff[4];
#pragma unroll
    for (int ks = 0; ks < 4; ++ks)
        boff[ks] = (uint32_t)(ks * 16 + lane_r) * 256;   // 256 B per B row

    float accM[2][8][4];
#pragma unroll
    for (int t = 0; t < 2; ++t)
#pragma unroll
        for (int nt = 0; nt < 8; ++nt)
#pragma unroll
            for (int i = 0; i < 4; ++i) accM[t][nt][i] = 0.f;

    int st = 0, stn = 2;   // rotating stage indices: current, next-to-load
    for (int kt = 0; kt < 32; ++kt) {
        CP_WAIT1();
        __syncthreads();

        const uint32_t Ab = sb + st * STG_BYTES;
        const uint32_t Bb = Ab + 8192;

        if (kt + 2 < 32) load_stage(kbase + kt + 2, stn);
        CP_COMMIT();

#pragma unroll
        for (int ks = 0; ks < 4; ++ks) {
            uint32_t af[2][4], bfr[4][4];
#pragma unroll
            for (int t = 0; t < 2; ++t) {
                uint32_t co = ((uint32_t)(ks * 2 + chh) ^ axr[t]) * 16;
                ldsm4(af[t], Ab + arow[t] + co);
            }
#pragma unroll
            for (int bb = 0; bb < 4; ++bb)
                ldsm4t(bfr[bb], Bb + boff[ks] + bcol[bb]);
#pragma unroll
            for (int t = 0; t < 2; ++t)
#pragma unroll
                for (int nt = 0; nt < 8; ++nt)
                    mma_f16(accM[t][nt], af[t], &bfr[nt >> 1][(nt & 1) * 2]);
        }

        st  = (st  == NS - 1) ? 0 : st + 1;
        stn = (stn == NS - 1) ? 0 : stn + 1;
    }

    // epilogue: atomic accumulate partials; k-half 0 contributes bias
    const bool addb = (blockIdx.z == 0);
#pragma unroll
    for (int t = 0; t < 2; ++t) {
        int row0 = m0 + wm * 32 + t * 16 + (lane >> 2);
#pragma unroll
        for (int nt = 0; nt < 8; ++nt) {
            int col = n0 + wn * 64 + nt * 8 + (lane & 3) * 2;
            float2 b = *(const float2*)(bias + col);
            float a0 = accM[t][nt][0], a1 = accM[t][nt][1];
            float a2 = accM[t][nt][2], a3 = accM[t][nt][3];
            if (addb) { a0 += b.x; a1 += b.y; a2 += b.x; a3 += b.y; }
            atomicAdd(C + (size_t)row0 * NNV + col,           a0);
            atomicAdd(C + (size_t)row0 * NNV + col + 1,       a1);
            atomicAdd(C + (size_t)(row0 + 8) * NNV + col,     a2);
            atomicAdd(C + (size_t)(row0 + 8) * NNV + col + 1, a3);
        }
    }
}

// ---------------------------------------------------------------------------
// Host. Inputs: x, scales, zero_points, bias, qweight
// ---------------------------------------------------------------------------
extern "C" void kernel_launch(void* const* d_in, const int* in_sizes, int n_in,
                              void* d_out, int out_size)
{
    const float* x      = (const float*)d_in[0];
    const float* scales = (const float*)d_in[1];
    const float* zp     = (const float*)d_in[2];
    const float* bias   = (const float*)d_in[3];
    const int*   qw     = (const int*)d_in[4];
    float*       out    = (float*)d_out;

    // zero C for atomic partial accumulation (async: graph-capturable)
    cudaMemsetAsync(out, 0, (size_t)MMV * NNV * sizeof(float));

    prep_kernel<<<12288, 256>>>((const float4*)x, qw, zp, scales);

    static bool attr_set = false;
    if (!attr_set) {
        cudaFuncSetAttribute(gemm_kernel, cudaFuncAttributeMaxDynamicSharedMemorySize, SMEM_TOTAL);
        attr_set = true;
    }
    gemm_kernel<<<dim3(NNV / 128, MMV / 64, 2), 128, SMEM_TOTAL>>>(bias, out);
}

// round 13
// speedup vs baseline: 1.0311x; 1.0311x over previous
#include <cuda_runtime.h>
#include <cuda_fp16.h>
#include <cstdint>

#define MMV 2048
#define NNV 4096
#define KKV 4096

// Scratch (__device__ globals; no allocations allowed)
__device__ __align__(16) __half g_xh[(size_t)MMV * KKV];  // fp16(x)
__device__ __align__(16) __half g_wd[(size_t)KKV * NNV];  // fp16(s*(q-z)), [K][N]

// ---------------------------------------------------------------------------
// asm helpers
// ---------------------------------------------------------------------------
__device__ __forceinline__ void ldsm4(uint32_t* r, uint32_t addr) {
    asm volatile("ldmatrix.sync.aligned.m8n8.x4.shared.b16 {%0,%1,%2,%3}, [%4];"
                 : "=r"(r[0]), "=r"(r[1]), "=r"(r[2]), "=r"(r[3]) : "r"(addr));
}
__device__ __forceinline__ void ldsm4t(uint32_t* r, uint32_t addr) {
    asm volatile("ldmatrix.sync.aligned.m8n8.x4.trans.shared.b16 {%0,%1,%2,%3}, [%4];"
                 : "=r"(r[0]), "=r"(r[1]), "=r"(r[2]), "=r"(r[3]) : "r"(addr));
}
__device__ __forceinline__ void mma_f16(float* c, const uint32_t* a, const uint32_t* b) {
    asm volatile("mma.sync.aligned.m16n8k16.row.col.f32.f16.f16.f32 "
                 "{%0,%1,%2,%3}, {%4,%5,%6,%7}, {%8,%9}, {%0,%1,%2,%3};"
                 : "+f"(c[0]), "+f"(c[1]), "+f"(c[2]), "+f"(c[3])
                 : "r"(a[0]), "r"(a[1]), "r"(a[2]), "r"(a[3]), "r"(b[0]), "r"(b[1]));
}
__device__ __forceinline__ void cpa16(uint32_t s, const void* g) {
    asm volatile("cp.async.cg.shared.global [%0], [%1], 16;" :: "r"(s), "l"(g));
}
#define CP_COMMIT() asm volatile("cp.async.commit_group;" ::: "memory")
#define CP_WAIT1()  asm volatile("cp.async.wait_group 1;" ::: "memory")

// ---------------------------------------------------------------------------
// Fused prep: x->fp16; W unpack to fp16(s*(q-z))   (unchanged from R9)
// ---------------------------------------------------------------------------
__global__ void prep_kernel(const float4* __restrict__ x4,
                            const int* __restrict__ qw,
                            const float* __restrict__ zp,
                            const float* __restrict__ scales)
{
    if (blockIdx.x < 8192) {
        size_t i = (size_t)blockIdx.x * blockDim.x + threadIdx.x;   // over M*K/4
        float4 v = x4[i];
        __align__(8) __half h[4];
        h[0] = __float2half_rn(v.x); h[1] = __float2half_rn(v.y);
        h[2] = __float2half_rn(v.z); h[3] = __float2half_rn(v.w);
        ((uint2*)g_xh)[i] = *(uint2*)h;
    } else {
        int T = (blockIdx.x - 8192) * blockDim.x + threadIdx.x;     // < 512*2048
        int np = T & (NNV / 2 - 1);
        int kp = T >> 11;
        int g  = kp >> 4;
        int n0 = np * 2;
        float z0 = fminf(fmaxf(rintf(zp[g * NNV + n0]),     0.0f), 15.0f);
        float z1 = fminf(fmaxf(rintf(zp[g * NNV + n0 + 1]), 0.0f), 15.0f);
        float s0 = fminf(fmaxf(scales[g * NNV + n0],     1e-5f), 1e4f);
        float s1 = fminf(fmaxf(scales[g * NNV + n0 + 1], 1e-5f), 1e4f);
        int q0 = qw[(size_t)kp * NNV + n0];
        int q1 = qw[(size_t)kp * NNV + n0 + 1];
#pragma unroll
        for (int j = 0; j < 8; ++j) {
            float w0 = (float)((q0 >> (4 * j)) & 15);
            float w1 = (float)((q1 >> (4 * j)) & 15);
            __half2 o = __floats2half2_rn((w0 - z0) * s0, (w1 - z1) * s1);
            *(__half2*)(g_wd + (size_t)(kp * 8 + j) * NNV + n0) = o;
        }
    }
}

// ---------------------------------------------------------------------------
// GEMM: C = xh @ Wd + bias.
// CTA tile 128x128, BK=64, 4 warps (2m x 2n), warp tile 64x64.
// Traffic: 1.0 GB total through L2 (was 1.5 GB at 64x128) — the R10-R12
// regressions showed the kernel sits near the LTS bandwidth cap.
// NS=3 stages x (A 16K | B 16K) = 96 KB smem; 2 CTAs/SM (256-reg budget).
// ---------------------------------------------------------------------------
#define NS 3
#define STG_BYTES 32768
#define SMEM_TOTAL (NS * STG_BYTES)   // 98304

__global__ void __launch_bounds__(128, 2)
gemm_kernel(const float* __restrict__ bias,
            float* __restrict__ C)
{
    extern __shared__ __align__(16) char smem[];
    const uint32_t sb = (uint32_t)__cvta_generic_to_shared(smem);
    const int tid = threadIdx.x, lane = tid & 31, wid = tid >> 5;
    const int wm = wid & 1, wn = wid >> 1;
    const int m0 = blockIdx.y * 128, n0 = blockIdx.x * 128;

    // loader: A 128x64 fp16 (1024 x 16B chunks), B 64x128 fp16 (1024 chunks)
    auto load_stage = [&](int kt, int st) {
        uint32_t base = sb + st * STG_BYTES;
#pragma unroll
        for (int j = 0; j < 8; ++j) {
            int p = tid + j * 128;
            int r = p >> 3, c = p & 7;
            uint32_t so = base + (uint32_t)(r * 8 + (c ^ (r & 7))) * 16;
            cpa16(so, g_xh + (size_t)(m0 + r) * KKV + kt * 64 + c * 8);
        }
#pragma unroll
        for (int j = 0; j < 8; ++j) {
            int p = tid + j * 128;
            int r = p >> 4, c = p & 15;
            uint32_t so = base + 16384 + (uint32_t)(r * 16 + (c ^ (r & 7))) * 16;
            cpa16(so, g_wd + (size_t)(kt * 64 + r) * NNV + n0 + c * 8);
        }
    };

    // prefill 2 stages
    load_stage(0, 0); CP_COMMIT();
    load_stage(1, 1); CP_COMMIT();

    // ldmatrix address precompute
    const int lane_r = lane & 15, chh = lane >> 4;
    uint32_t arow[4], axr[4];
#pragma unroll
    for (int t = 0; t < 4; ++t) {
        int r = wm * 64 + t * 16 + lane_r;
        arow[t] = (uint32_t)r * 128;            // 128 B per A row
        axr[t]  = (uint32_t)(r & 7);
    }
    const uint32_t xb = (uint32_t)(lane_r & 7);
    uint32_t bcol[4];
#pragma unroll
    for (int bb = 0; bb < 4; ++bb)
        bcol[bb] = (uint32_t)(wn * 8 + (((uint32_t)(bb * 2 + chh)) ^ xb)) * 16;
    uint32_t boff[4];
#pragma unroll
    for (int ks = 0; ks < 4; ++ks)
        boff[ks] = (uint32_t)(ks * 16 + lane_r) * 256;   // 256 B per B row

    float accM[4][8][4];
#pragma unroll
    for (int t = 0; t < 4; ++t)
#pragma unroll
        for (int nt = 0; nt < 8; ++nt)
#pragma unroll
            for (int i = 0; i < 4; ++i) accM[t][nt][i] = 0.f;

    int st = 0, stn = 2;   // rotating stage indices: current, next-to-load
    for (int kt = 0; kt < 64; ++kt) {
        CP_WAIT1();
        __syncthreads();

        const uint32_t Ab = sb + st * STG_BYTES;
        const uint32_t Bb = Ab + 16384;

        if (kt + 2 < 64) load_stage(kt + 2, stn);
        CP_COMMIT();

#pragma unroll
        for (int ks = 0; ks < 4; ++ks) {
            uint32_t af[4][4], bfr[4][4];
#pragma unroll
            for (int t = 0; t < 4; ++t) {
                uint32_t co = ((uint32_t)(ks * 2 + chh) ^ axr[t]) * 16;
                ldsm4(af[t], Ab + arow[t] + co);
            }
#pragma unroll
            for (int bb = 0; bb < 4; ++bb)
                ldsm4t(bfr[bb], Bb + boff[ks] + bcol[bb]);
#pragma unroll
            for (int t = 0; t < 4; ++t)
#pragma unroll
                for (int nt = 0; nt < 8; ++nt)
                    mma_f16(accM[t][nt], af[t], &bfr[nt >> 1][(nt & 1) * 2]);
        }

        st  = (st  == NS - 1) ? 0 : st + 1;
        stn = (stn == NS - 1) ? 0 : stn + 1;
    }

    // epilogue
#pragma unroll
    for (int t = 0; t < 4; ++t) {
        int row0 = m0 + wm * 64 + t * 16 + (lane >> 2);
#pragma unroll
        for (int nt = 0; nt < 8; ++nt) {
            int col = n0 + wn * 64 + nt * 8 + (lane & 3) * 2;
            float2 b = *(const float2*)(bias + col);
            float2 o0, o1;
            o0.x = accM[t][nt][0] + b.x;  o0.y = accM[t][nt][1] + b.y;
            o1.x = accM[t][nt][2] + b.x;  o1.y = accM[t][nt][3] + b.y;
            *(float2*)(C + (size_t)row0 * NNV + col)       = o0;
            *(float2*)(C + (size_t)(row0 + 8) * NNV + col) = o1;
        }
    }
}

// ---------------------------------------------------------------------------
// Host. Inputs: x, scales, zero_points, bias, qweight
// ---------------------------------------------------------------------------
extern "C" void kernel_launch(void* const* d_in, const int* in_sizes, int n_in,
                              void* d_out, int out_size)
{
    const float* x      = (const float*)d_in[0];
    const float* scales = (const float*)d_in[1];
    const float* zp     = (const float*)d_in[2];
    const float* bias   = (const float*)d_in[3];
    const int*   qw     = (const int*)d_in[4];
    float*       out    = (float*)d_out;

    prep_kernel<<<12288, 256>>>((const float4*)x, qw, zp, scales);

    static bool attr_set = false;
    if (!attr_set) {
        cudaFuncSetAttribute(gemm_kernel, cudaFuncAttributeMaxDynamicSharedMemorySize, SMEM_TOTAL);
        attr_set = true;
    }
    gemm_kernel<<<dim3(NNV / 128, MMV / 128), 128, SMEM_TOTAL>>>(bias, out);
}

// round 14
// speedup vs baseline: 1.0819x; 1.0493x over previous
#include <cuda_runtime.h>
#include <cuda_fp16.h>
#include <cstdint>

#define MMV 2048
#define NNV 4096
#define KKV 4096

#define FULL_CTAS 888          // 2 exact waves at 3 CTAs/SM x 148 SMs
#define TAIL_TILES (1024 - FULL_CTAS)   // 136
#define SPLITS 3
#define GRID_TOTAL (FULL_CTAS + TAIL_TILES * SPLITS)   // 1296

// Scratch (__device__ globals; no allocations allowed)
__device__ __align__(16) __half g_xh[(size_t)MMV * KKV];  // fp16(x)
__device__ __align__(16) __half g_wd[(size_t)KKV * NNV];  // fp16(s*(q-z)), [K][N]

// ---------------------------------------------------------------------------
// asm helpers
// ---------------------------------------------------------------------------
__device__ __forceinline__ void ldsm4(uint32_t* r, uint32_t addr) {
    asm volatile("ldmatrix.sync.aligned.m8n8.x4.shared.b16 {%0,%1,%2,%3}, [%4];"
                 : "=r"(r[0]), "=r"(r[1]), "=r"(r[2]), "=r"(r[3]) : "r"(addr));
}
__device__ __forceinline__ void ldsm4t(uint32_t* r, uint32_t addr) {
    asm volatile("ldmatrix.sync.aligned.m8n8.x4.trans.shared.b16 {%0,%1,%2,%3}, [%4];"
                 : "=r"(r[0]), "=r"(r[1]), "=r"(r[2]), "=r"(r[3]) : "r"(addr));
}
__device__ __forceinline__ void mma_f16(float* c, const uint32_t* a, const uint32_t* b) {
    asm volatile("mma.sync.aligned.m16n8k16.row.col.f32.f16.f16.f32 "
                 "{%0,%1,%2,%3}, {%4,%5,%6,%7}, {%8,%9}, {%0,%1,%2,%3};"
                 : "+f"(c[0]), "+f"(c[1]), "+f"(c[2]), "+f"(c[3])
                 : "r"(a[0]), "r"(a[1]), "r"(a[2]), "r"(a[3]), "r"(b[0]), "r"(b[1]));
}
__device__ __forceinline__ void cpa16(uint32_t s, const void* g) {
    asm volatile("cp.async.cg.shared.global [%0], [%1], 16;" :: "r"(s), "l"(g));
}
#define CP_COMMIT() asm volatile("cp.async.commit_group;" ::: "memory")
#define CP_WAIT1()  asm volatile("cp.async.wait_group 1;" ::: "memory")

// ---------------------------------------------------------------------------
// Fused prep: x->fp16; W unpack to fp16(s*(q-z))   (unchanged)
// ---------------------------------------------------------------------------
__global__ void prep_kernel(const float4* __restrict__ x4,
                            const int* __restrict__ qw,
                            const float* __restrict__ zp,
                            const float* __restrict__ scales)
{
    if (blockIdx.x < 8192) {
        size_t i = (size_t)blockIdx.x * blockDim.x + threadIdx.x;   // over M*K/4
        float4 v = x4[i];
        __align__(8) __half h[4];
        h[0] = __float2half_rn(v.x); h[1] = __float2half_rn(v.y);
        h[2] = __float2half_rn(v.z); h[3] = __float2half_rn(v.w);
        ((uint2*)g_xh)[i] = *(uint2*)h;
    } else {
        int T = (blockIdx.x - 8192) * blockDim.x + threadIdx.x;     // < 512*2048
        int np = T & (NNV / 2 - 1);
        int kp = T >> 11;
        int g  = kp >> 4;
        int n0 = np * 2;
        float z0 = fminf(fmaxf(rintf(zp[g * NNV + n0]),     0.0f), 15.0f);
        float z1 = fminf(fmaxf(rintf(zp[g * NNV + n0 + 1]), 0.0f), 15.0f);
        float s0 = fminf(fmaxf(scales[g * NNV + n0],     1e-5f), 1e4f);
        float s1 = fminf(fmaxf(scales[g * NNV + n0 + 1], 1e-5f), 1e4f);
        int q0 = qw[(size_t)kp * NNV + n0];
        int q1 = qw[(size_t)kp * NNV + n0 + 1];
#pragma unroll
        for (int j = 0; j < 8; ++j) {
            float w0 = (float)((q0 >> (4 * j)) & 15);
            float w1 = (float)((q1 >> (4 * j)) & 15);
            __half2 o = __floats2half2_rn((w0 - z0) * s0, (w1 - z1) * s1);
            *(__half2*)(g_wd + (size_t)(kp * 8 + j) * NNV + n0) = o;
        }
    }
}

// ---------------------------------------------------------------------------
// GEMM: C = xh @ Wd + bias. R9 microkernel: tile 64x128, BK=64, 4 warps
// (2m x 2n), warp tile 32x64, NS=3, 3 CTAs/SM.
// Tile-level scheduling: first 888 CTAs (= 2 exact waves of 444 slots) do
// full-K tiles with the untouched static loop + plain stores. The 136
// remaining tiles are split 3-ways in K across 408 tail CTAs (wave 3,
// ~22/64 of a tile each) that atomicAdd into pre-zeroed rows.
// ---------------------------------------------------------------------------
#define NS 3
#define STG_BYTES 24576
#define SMEM_TOTAL (NS * STG_BYTES)   // 73728

__global__ void __launch_bounds__(128, 3)
gemm_kernel(const float* __restrict__ bias,
            float* __restrict__ C)
{
    extern __shared__ __align__(16) char smem[];
    const uint32_t sb = (uint32_t)__cvta_generic_to_shared(smem);
    const int tid = threadIdx.x, lane = tid & 31, wid = tid >> 5;
    const int wm = wid & 1, wn = wid >> 1;

    const int idx = blockIdx.x;
    int tile, kbeg, kcnt, part;
    if (idx < FULL_CTAS) {
        tile = idx; kbeg = 0; kcnt = 64; part = -1;
    } else {
        int t = idx - FULL_CTAS;
        tile = FULL_CTAS + t / SPLITS;
        part = t % SPLITS;
        kbeg = (part == 0) ? 0 : (22 + 21 * (part - 1));   // [0,22) [22,43) [43,64)
        kcnt = (part == 0) ? 22 : 21;
    }
    const int m0 = (tile >> 5) * 64;       // tiles n-fastest (32 n-tiles per m-row)
    const int n0 = (tile & 31) * 128;

    // loader: A 64x64 fp16 (512 x 16B chunks), B 64x128 fp16 (1024 chunks)
    auto load_stage = [&](int kt, int st) {
        uint32_t base = sb + st * STG_BYTES;
#pragma unroll
        for (int j = 0; j < 4; ++j) {
            int q = tid + j * 128;
            int r = q >> 3, c = q & 7;
            uint32_t so = base + (uint32_t)(r * 8 + (c ^ (r & 7))) * 16;
            cpa16(so, g_xh + (size_t)(m0 + r) * KKV + kt * 64 + c * 8);
        }
#pragma unroll
        for (int j = 0; j < 8; ++j) {
            int q = tid + j * 128;
            int r = q >> 4, c = q & 15;
            uint32_t so = base + 8192 + (uint32_t)(r * 16 + (c ^ (r & 7))) * 16;
            cpa16(so, g_wd + (size_t)(kt * 64 + r) * NNV + n0 + c * 8);
        }
    };

    // prefill 2 stages (kcnt >= 21 always)
    load_stage(kbeg + 0, 0); CP_COMMIT();
    load_stage(kbeg + 1, 1); CP_COMMIT();

    // ldmatrix address precompute
    const int lane_r = lane & 15, chh = lane >> 4;
    uint32_t arow[2], axr[2];
#pragma unroll
    for (int t = 0; t < 2; ++t) {
        int r = wm * 32 + t * 16 + lane_r;
        arow[t] = (uint32_t)r * 128;            // 128 B per A row
        axr[t]  = (uint32_t)(r & 7);
    }
    const uint32_t xb = (uint32_t)(lane_r & 7);
    uint32_t bcol[4];
#pragma unroll
    for (int bb = 0; bb < 4; ++bb)
        bcol[bb] = (uint32_t)(wn * 8 + (((uint32_t)(bb * 2 + chh)) ^ xb)) * 16;
    uint32_t boff[4];
#pragma unroll
    for (int ks = 0; ks < 4; ++ks)
        boff[ks] = (uint32_t)(ks * 16 + lane_r) * 256;   // 256 B per B row

    float accM[2][8][4];
#pragma unroll
    for (int t = 0; t < 2; ++t)
#pragma unroll
        for (int nt = 0; nt < 8; ++nt)
#pragma unroll
            for (int i = 0; i < 4; ++i) accM[t][nt][i] = 0.f;

    int st = 0, stn = 2;

#define MAIN_BODY(KT_GLOBAL, HAVE_NEXT)                                        \
    {                                                                          \
        CP_WAIT1();                                                            \
        __syncthreads();                                                       \
        const uint32_t Ab = sb + st * STG_BYTES;                               \
        const uint32_t Bb = Ab + 8192;                                         \
        if (HAVE_NEXT) load_stage((KT_GLOBAL) + 2, stn);                       \
        CP_COMMIT();                                                           \
        _Pragma("unroll")                                                      \
        for (int ks = 0; ks < 4; ++ks) {                                       \
            uint32_t af[2][4], bfr[4][4];                                      \
            _Pragma("unroll")                                                  \
            for (int t = 0; t < 2; ++t) {                                      \
                uint32_t co = ((uint32_t)(ks * 2 + chh) ^ axr[t]) * 16;        \
                ldsm4(af[t], Ab + arow[t] + co);                               \
            }                                                                  \
            _Pragma("unroll")                                                  \
            for (int bb = 0; bb < 4; ++bb)                                     \
                ldsm4t(bfr[bb], Bb + boff[ks] + bcol[bb]);                     \
            _Pragma("unroll")                                                  \
            for (int t = 0; t < 2; ++t)                                        \
                _Pragma("unroll")                                              \
                for (int nt = 0; nt < 8; ++nt)                                 \
                    mma_f16(accM[t][nt], af[t], &bfr[nt >> 1][(nt & 1) * 2]);  \
        }                                                                      \
        st  = (st  == NS - 1) ? 0 : st + 1;                                    \
        stn = (stn == NS - 1) ? 0 : stn + 1;                                   \
    }

    if (idx < FULL_CTAS) {
        // static trip count: identical codegen to the proven R9 loop
        for (int kt = 0; kt < 64; ++kt)
            MAIN_BODY(kt, (kt + 2 < 64))
    } else {
        for (int kt = 0; kt < kcnt; ++kt)
            MAIN_BODY(kbeg + kt, (kt + 2 < kcnt))
    }
#undef MAIN_BODY

    // epilogue
    if (idx < FULL_CTAS) {
#pragma unroll
        for (int t = 0; t < 2; ++t) {
            int row0 = m0 + wm * 32 + t * 16 + (lane >> 2);
#pragma unroll
            for (int nt = 0; nt < 8; ++nt) {
                int col = n0 + wn * 64 + nt * 8 + (lane & 3) * 2;
                float2 b = *(const float2*)(bias + col);
                float2 o0, o1;
                o0.x = accM[t][nt][0] + b.x;  o0.y = accM[t][nt][1] + b.y;
                o1.x = accM[t][nt][2] + b.x;  o1.y = accM[t][nt][3] + b.y;
                *(float2*)(C + (size_t)row0 * NNV + col)       = o0;
                *(float2*)(C + (size_t)(row0 + 8) * NNV + col) = o1;
            }
        }
    } else {
        const bool addb = (part == 0);
#pragma unroll
        for (int t = 0; t < 2; ++t) {
            int row0 = m0 + wm * 32 + t * 16 + (lane >> 2);
#pragma unroll
            for (int nt = 0; nt < 8; ++nt) {
                int col = n0 + wn * 64 + nt * 8 + (lane & 3) * 2;
                float2 b = *(const float2*)(bias + col);
                float a0 = accM[t][nt][0], a1 = accM[t][nt][1];
                float a2 = accM[t][nt][2], a3 = accM[t][nt][3];
                if (addb) { a0 += b.x; a1 += b.y; a2 += b.x; a3 += b.y; }
                atomicAdd(C + (size_t)row0 * NNV + col,           a0);
                atomicAdd(C + (size_t)row0 * NNV + col + 1,       a1);
                atomicAdd(C + (size_t)(row0 + 8) * NNV + col,     a2);
                atomicAdd(C + (size_t)(row0 + 8) * NNV + col + 1, a3);
            }
        }
    }
}

// ---------------------------------------------------------------------------
// Host. Inputs: x, scales, zero_points, bias, qweight
// ---------------------------------------------------------------------------
extern "C" void kernel_launch(void* const* d_in, const int* in_sizes, int n_in,
                              void* d_out, int out_size)
{
    const float* x      = (const float*)d_in[0];
    const float* scales = (const float*)d_in[1];
    const float* zp     = (const float*)d_in[2];
    const float* bias   = (const float*)d_in[3];
    const int*   qw     = (const int*)d_in[4];
    float*       out    = (float*)d_out;

    // zero only the rows containing tail tiles (tile idx >= 888 -> m >= 1728)
    cudaMemsetAsync(out + (size_t)1728 * NNV, 0,
                    (size_t)(MMV - 1728) * NNV * sizeof(float));

    prep_kernel<<<12288, 256>>>((const float4*)x, qw, zp, scales);

    static bool attr_set = false;
    if (!attr_set) {
        cudaFuncSetAttribute(gemm_kernel, cudaFuncAttributeMaxDynamicSharedMemorySize, SMEM_TOTAL);
        attr_set = true;
    }
    gemm_kernel<<<GRID_TOTAL, 128, SMEM_TOTAL>>>(bias, out);
}

// round 15
// speedup vs baseline: 1.1227x; 1.0377x over previous
#include <cuda_runtime.h>
#include <cuda_fp16.h>
#include <cstdint>

#define MMV 2048
#define NNV 4096
#define KKV 4096

// Scratch (__device__ globals; no allocations allowed)
__device__ __align__(16) __half g_xh[(size_t)MMV * KKV];  // fp16(x)
__device__ __align__(16) __half g_wd[(size_t)KKV * NNV];  // fp16(s*(q-z)), [K][N]

// ---------------------------------------------------------------------------
// asm helpers
// ---------------------------------------------------------------------------
__device__ __forceinline__ void ldsm4(uint32_t* r, uint32_t addr) {
    asm volatile("ldmatrix.sync.aligned.m8n8.x4.shared.b16 {%0,%1,%2,%3}, [%4];"
                 : "=r"(r[0]), "=r"(r[1]), "=r"(r[2]), "=r"(r[3]) : "r"(addr));
}
__device__ __forceinline__ void ldsm4t(uint32_t* r, uint32_t addr) {
    asm volatile("ldmatrix.sync.aligned.m8n8.x4.trans.shared.b16 {%0,%1,%2,%3}, [%4];"
                 : "=r"(r[0]), "=r"(r[1]), "=r"(r[2]), "=r"(r[3]) : "r"(addr));
}
__device__ __forceinline__ void mma_f16(float* c, const uint32_t* a, const uint32_t* b) {
    asm volatile("mma.sync.aligned.m16n8k16.row.col.f32.f16.f16.f32 "
                 "{%0,%1,%2,%3}, {%4,%5,%6,%7}, {%8,%9}, {%0,%1,%2,%3};"
                 : "+f"(c[0]), "+f"(c[1]), "+f"(c[2]), "+f"(c[3])
                 : "r"(a[0]), "r"(a[1]), "r"(a[2]), "r"(a[3]), "r"(b[0]), "r"(b[1]));
}
__device__ __forceinline__ void cpa16(uint32_t s, const void* g) {
    asm volatile("cp.async.cg.shared.global [%0], [%1], 16;" :: "r"(s), "l"(g));
}
#define CP_COMMIT() asm volatile("cp.async.commit_group;" ::: "memory")
#define CP_WAIT1()  asm volatile("cp.async.wait_group 1;" ::: "memory")

// ---------------------------------------------------------------------------
// Fused prep, one launch:
//   blocks [0,4096):     x -> fp16, 8 floats in (2x float4), one uint4 out
//   blocks [4096,5120):  W unpack, 8 n per thread -> 8x uint4 coalesced stores
// Per-element math identical to prior rounds (rel_err invariant).
// ---------------------------------------------------------------------------
__global__ void prep_kernel(const float4* __restrict__ x4,
                            const int* __restrict__ qw,
                            const float* __restrict__ zp,
                            const float* __restrict__ scales)
{
    if (blockIdx.x < 4096) {
        size_t i = (size_t)blockIdx.x * blockDim.x + threadIdx.x;   // over M*K/8
        float4 a = x4[2 * i], b = x4[2 * i + 1];
        __half2 h0 = __floats2half2_rn(a.x, a.y);
        __half2 h1 = __floats2half2_rn(a.z, a.w);
        __half2 h2 = __floats2half2_rn(b.x, b.y);
        __half2 h3 = __floats2half2_rn(b.z, b.w);
        uint4 o;
        o.x = *(uint32_t*)&h0; o.y = *(uint32_t*)&h1;
        o.z = *(uint32_t*)&h2; o.w = *(uint32_t*)&h3;
        ((uint4*)g_xh)[i] = o;
    } else {
        // thread: one kp (8 k-rows) x 8 consecutive n
        int T = (int)((blockIdx.x - 4096) * blockDim.x + threadIdx.x); // < 512*512
        int ng = T & 511;           // n-group (8 n's)
        int kp = T >> 9;            // packed row 0..511
        int g  = kp >> 4;           // GROUP=128 -> 16 packed rows per group
        int n0 = ng * 8;

        const float4* zp4 = (const float4*)(zp     + (size_t)g * NNV + n0);
        const float4* sc4 = (const float4*)(scales + (size_t)g * NNV + n0);
        float4 za = zp4[0], zb = zp4[1];
        float4 sa = sc4[0], sb = sc4[1];
        float zv[8] = {za.x, za.y, za.z, za.w, zb.x, zb.y, zb.z, zb.w};
        float sv[8] = {sa.x, sa.y, sa.z, sa.w, sb.x, sb.y, sb.z, sb.w};
#pragma unroll
        for (int i = 0; i < 8; ++i) {
            zv[i] = fminf(fmaxf(rintf(zv[i]), 0.0f), 15.0f);
            sv[i] = fminf(fmaxf(sv[i], 1e-5f), 1e4f);
        }
        int q[8];
#pragma unroll
        for (int i = 0; i < 8; ++i)
            q[i] = qw[(size_t)kp * NNV + n0 + i];

#pragma unroll
        for (int j = 0; j < 8; ++j) {       // k within the packed int
            __align__(16) __half h[8];
#pragma unroll
            for (int i = 0; i < 8; ++i) {
                float w = (float)((q[i] >> (4 * j)) & 15);
                h[i] = __float2half_rn((w - zv[i]) * sv[i]);
            }
            *(uint4*)(g_wd + (size_t)(kp * 8 + j) * NNV + n0) = *(uint4*)h;
        }
    }
}

// ---------------------------------------------------------------------------
// GEMM: C = xh @ Wd + bias — EXACT R9 kernel (best measured: 154.6 us GEMM).
// CTA tile 64x128, BK=64, 4 warps (2m x 2n), warp tile 32x64.
// NS=3 stages x (A 8K | B 16K) = 73.7 KB smem; 3 CTAs/SM.
// ---------------------------------------------------------------------------
#define NS 3
#define STG_BYTES 24576
#define SMEM_TOTAL (NS * STG_BYTES)   // 73728

__global__ void __launch_bounds__(128, 3)
gemm_kernel(const float* __restrict__ bias,
            float* __restrict__ C)
{
    extern __shared__ __align__(16) char smem[];
    const uint32_t sb = (uint32_t)__cvta_generic_to_shared(smem);
    const int tid = threadIdx.x, lane = tid & 31, wid = tid >> 5;
    const int wm = wid & 1, wn = wid >> 1;
    const int m0 = blockIdx.y * 64, n0 = blockIdx.x * 128;

    // loader: A 64x64 fp16 (512 x 16B chunks), B 64x128 fp16 (1024 chunks)
    auto load_stage = [&](int kt, int st) {
        uint32_t base = sb + st * STG_BYTES;
#pragma unroll
        for (int j = 0; j < 4; ++j) {
            int q = tid + j * 128;
            int r = q >> 3, c = q & 7;
            uint32_t so = base + (uint32_t)(r * 8 + (c ^ (r & 7))) * 16;
            cpa16(so, g_xh + (size_t)(m0 + r) * KKV + kt * 64 + c * 8);
        }
#pragma unroll
        for (int j = 0; j < 8; ++j) {
            int q = tid + j * 128;
            int r = q >> 4, c = q & 15;
            uint32_t so = base + 8192 + (uint32_t)(r * 16 + (c ^ (r & 7))) * 16;
            cpa16(so, g_wd + (size_t)(kt * 64 + r) * NNV + n0 + c * 8);
        }
    };

    // prefill 2 stages
    load_stage(0, 0); CP_COMMIT();
    load_stage(1, 1); CP_COMMIT();

    // ldmatrix address precompute
    const int lane_r = lane & 15, chh = lane >> 4;
    uint32_t arow[2], axr[2];
#pragma unroll
    for (int t = 0; t < 2; ++t) {
        int r = wm * 32 + t * 16 + lane_r;
        arow[t] = (uint32_t)r * 128;            // 128 B per A row
        axr[t]  = (uint32_t)(r & 7);
    }
    const uint32_t xb = (uint32_t)(lane_r & 7);
    uint32_t bcol[4];
#pragma unroll
    for (int bb = 0; bb < 4; ++bb)
        bcol[bb] = (uint32_t)(wn * 8 + (((uint32_t)(bb * 2 + chh)) ^ xb)) * 16;
    uint32_t boff[4];
#pragma unroll
    for (int ks = 0; ks < 4; ++ks)
        boff[ks] = (uint32_t)(ks * 16 + lane_r) * 256;   // 256 B per B row

    float accM[2][8][4];
#pragma unroll
    for (int t = 0; t < 2; ++t)
#pragma unroll
        for (int nt = 0; nt < 8; ++nt)
#pragma unroll
            for (int i = 0; i < 4; ++i) accM[t][nt][i] = 0.f;

    int st = 0, stn = 2;   // rotating stage indices: current, next-to-load
    for (int kt = 0; kt < 64; ++kt) {
        CP_WAIT1();
        __syncthreads();

        const uint32_t Ab = sb + st * STG_BYTES;
        const uint32_t Bb = Ab + 8192;

        if (kt + 2 < 64) load_stage(kt + 2, stn);
        CP_COMMIT();

#pragma unroll
        for (int ks = 0; ks < 4; ++ks) {
            uint32_t af[2][4], bfr[4][4];
#pragma unroll
            for (int t = 0; t < 2; ++t) {
                uint32_t co = ((uint32_t)(ks * 2 + chh) ^ axr[t]) * 16;
                ldsm4(af[t], Ab + arow[t] + co);
            }
#pragma unroll
            for (int bb = 0; bb < 4; ++bb)
                ldsm4t(bfr[bb], Bb + boff[ks] + bcol[bb]);
#pragma unroll
            for (int t = 0; t < 2; ++t)
#pragma unroll
                for (int nt = 0; nt < 8; ++nt)
                    mma_f16(accM[t][nt], af[t], &bfr[nt >> 1][(nt & 1) * 2]);
        }

        st  = (st  == NS - 1) ? 0 : st + 1;
        stn = (stn == NS - 1) ? 0 : stn + 1;
    }

    // epilogue
#pragma unroll
    for (int t = 0; t < 2; ++t) {
        int row0 = m0 + wm * 32 + t * 16 + (lane >> 2);
#pragma unroll
        for (int nt = 0; nt < 8; ++nt) {
            int col = n0 + wn * 64 + nt * 8 + (lane & 3) * 2;
            float2 b = *(const float2*)(bias + col);
            float2 o0, o1;
            o0.x = accM[t][nt][0] + b.x;  o0.y = accM[t][nt][1] + b.y;
            o1.x = accM[t][nt][2] + b.x;  o1.y = accM[t][nt][3] + b.y;
            *(float2*)(C + (size_t)row0 * NNV + col)       = o0;
            *(float2*)(C + (size_t)(row0 + 8) * NNV + col) = o1;
        }
    }
}

// ---------------------------------------------------------------------------
// Host. Inputs: x, scales, zero_points, bias, qweight
// ---------------------------------------------------------------------------
extern "C" void kernel_launch(void* const* d_in, const int* in_sizes, int n_in,
                              void* d_out, int out_size)
{
    const float* x      = (const float*)d_in[0];
    const float* scales = (const float*)d_in[1];
    const float* zp     = (const float*)d_in[2];
    const float* bias   = (const float*)d_in[3];
    const int*   qw     = (const int*)d_in[4];
    float*       out    = (float*)d_out;

    prep_kernel<<<5120, 256>>>((const float4*)x, qw, zp, scales);

    static bool attr_set = false;
    if (!attr_set) {
        cudaFuncSetAttribute(gemm_kernel, cudaFuncAttributeMaxDynamicSharedMemorySize, SMEM_TOTAL);
        attr_set = true;
    }
    gemm_kernel<<<dim3(NNV / 128, MMV / 64), 128, SMEM_TOTAL>>>(bias, out);
}